// round 9
// baseline (speedup 1.0000x reference)
#include <cuda_runtime.h>
#include <cstdint>

#define KSZ 5
#define NBUCKETS 25
#define BATCH 8
#define CHANNELS 96
#define HEIGHT 192
#define WIDTH 192

#define BTX 16
#define BTY 16
#define NTHREADS (BTX*BTY)
#define PX 4
#define CH 2
#define NBUF 4
#define TILE_OW (BTX*PX)  // 64
#define TILE_OH BTY       // 16
#define HALO 2
#define TROWS (TILE_OH + 2*HALO)   // 20
#define TCOLS (TILE_OW + 2*HALO)   // 68
#define TSTRIDE 72                 // floats per row (16B-aligned)
#define TILE_FLOATS (TROWS * TSTRIDE)
#define NPAIRS (TROWS * (TCOLS/2))  // 680 8-byte pairs
#define NITER (CHANNELS / CH)       // 48
#define NSLOT 3                     // ceil(680/256)

__device__ __forceinline__ void cp_async8(uint32_t smem_dst, const void* gptr, int src_bytes) {
    asm volatile("cp.async.ca.shared.global [%0], [%1], 8, %2;\n"
                 :: "r"(smem_dst), "l"(gptr), "r"(src_bytes));
}
__device__ __forceinline__ void cp_async_commit() {
    asm volatile("cp.async.commit_group;\n" ::: "memory");
}
template <int N>
__device__ __forceinline__ void cp_async_wait() {
    asm volatile("cp.async.wait_group %0;\n" :: "n"(N) : "memory");
}

// Packed dual-FMA (Blackwell FFMA2) — only reachable via PTX fma.rn.f32x2.
__device__ __forceinline__ float2 ffma2(float2 a, float2 b, float2 c) {
    unsigned long long au = *reinterpret_cast<unsigned long long*>(&a);
    unsigned long long bu = *reinterpret_cast<unsigned long long*>(&b);
    unsigned long long cu = *reinterpret_cast<unsigned long long*>(&c);
    unsigned long long du;
    asm("fma.rn.f32x2 %0, %1, %2, %3;" : "=l"(du) : "l"(au), "l"(bu), "l"(cu));
    return *reinterpret_cast<float2*>(&du);
}

__global__ __launch_bounds__(NTHREADS, 2) void csconv2d_kernel(
    const float* __restrict__ input,        // [B,C,H,W]
    const float* __restrict__ kernel_bank,  // [25,5,5]
    const int* __restrict__ buckets,        // [B,H,W] int32
    float* __restrict__ output)             // [B,C,H,W]
{
    __shared__ __align__(16) float s_tile[NBUF][CH][TILE_FLOATS];
    __shared__ __align__(16) float s_bank[640];

    const int tx = threadIdx.x;
    const int ty = threadIdx.y;
    const int tid = ty * BTX + tx;

    const int w0 = blockIdx.x * TILE_OW;
    const int h0 = blockIdx.y * TILE_OH;
    const int b  = blockIdx.z;

    const int h = h0 + ty;
    const int wbase = w0 + PX * tx;

    for (int i = tid; i < NBUCKETS * KSZ * KSZ; i += NTHREADS)
        s_bank[i] = kernel_bank[i];
    __syncthreads();

    const int4 bk4 = *reinterpret_cast<const int4*>(
        &buckets[((long long)b * HEIGHT + h) * WIDTH + wbase]);
    int bkt[PX] = {bk4.x, bk4.y, bk4.z, bk4.w};
    #pragma unroll
    for (int p = 0; p < PX; p++)
        bkt[p] = min(max(bkt[p], 0), NBUCKETS - 1);

    // Even taps (j=0,2,4) packed per pixel-pair: wp0 for pixels (0,1), wp1 for (2,3).
    // Odd taps (j=1,3) scalar per pixel. Total = 60 + 40 = 100 registers.
    float2 wp0[15], wp1[15];
    float  wodd[PX][10];
    #pragma unroll
    for (int i = 0; i < KSZ; i++) {
        #pragma unroll
        for (int e = 0; e < 3; e++) {
            const int t = i * KSZ + 2 * e;
            wp0[i * 3 + e] = make_float2(s_bank[bkt[0] * 25 + t], s_bank[bkt[1] * 25 + t]);
            wp1[i * 3 + e] = make_float2(s_bank[bkt[2] * 25 + t], s_bank[bkt[3] * 25 + t]);
        }
        #pragma unroll
        for (int o = 0; o < 2; o++) {
            const int t = i * KSZ + 1 + 2 * o;
            #pragma unroll
            for (int p = 0; p < PX; p++)
                wodd[p][i * 2 + o] = s_bank[bkt[p] * 25 + t];
        }
    }

    const float* inb  = input  + (size_t)b * CHANNELS * HEIGHT * WIDTH;
    float*       outb = output + (size_t)b * CHANNELS * HEIGHT * WIDTH;

    const uint32_t s_tile_base = (uint32_t)__cvta_generic_to_shared(&s_tile[0][0][0]);

    // Iteration-invariant fill slots.
    int      g_rel[NSLOT];
    uint32_t s_rel[NSLOT];
    int      nbytes[NSLOT];
    #pragma unroll
    for (int s = 0; s < NSLOT; s++) {
        const int idx = tid + s * NTHREADS;
        if (idx < NPAIRS) {
            const int r   = idx / (TCOLS / 2);
            const int col = (idx % (TCOLS / 2)) * 2;
            const int gh = h0 + r - HALO;
            const int gw = w0 + col - HALO;
            const bool ok = ((unsigned)gh < HEIGHT) & ((unsigned)gw < WIDTH);
            g_rel[s]  = ok ? (gh * WIDTH + gw) : 0;
            s_rel[s]  = (uint32_t)((r * TSTRIDE + col) * 4);
            nbytes[s] = ok ? 8 : 0;
        } else {
            g_rel[s] = 0; s_rel[s] = 0; nbytes[s] = -1;
        }
    }

    auto issue_pair = [&](int c0, int buf) {
        #pragma unroll
        for (int cc = 0; cc < CH; cc++) {
            const float* chan = inb + (size_t)(c0 + cc) * (HEIGHT * WIDTH);
            const uint32_t sbase = s_tile_base
                + (uint32_t)((buf * CH + cc) * TILE_FLOATS * 4);
            #pragma unroll
            for (int s = 0; s < NSLOT; s++)
                if (nbytes[s] >= 0)
                    cp_async8(sbase + s_rel[s], chan + g_rel[s], nbytes[s]);
        }
        cp_async_commit();
    };

    issue_pair(0, 0);
    issue_pair(CH, 1);
    issue_pair(2 * CH, 2);

    #pragma unroll 1
    for (int it = 0; it < NITER; it++) {
        const int buf = it & (NBUF - 1);
        const int c0 = it * CH;

        const int rem = (NITER - 1) - it;
        if (rem >= 2)      cp_async_wait<2>();
        else if (rem == 1) cp_async_wait<1>();
        else               cp_async_wait<0>();
        __syncthreads();

        if (it + 3 < NITER)
            issue_pair(c0 + 3 * CH, (it + 3) & (NBUF - 1));

        float2 acc01[CH], acc23[CH];
        #pragma unroll
        for (int cc = 0; cc < CH; cc++) {
            acc01[cc] = make_float2(0.f, 0.f);
            acc23[cc] = make_float2(0.f, 0.f);
        }

        #pragma unroll
        for (int i = 0; i < KSZ; i++) {
            #pragma unroll
            for (int cc = 0; cc < CH; cc++) {
                const float* row = &s_tile[buf][cc][(ty + i) * TSTRIDE + PX * tx];
                // 16B-aligned: free even register pairs.
                const float2 p01 = *reinterpret_cast<const float2*>(row);
                const float2 p23 = *reinterpret_cast<const float2*>(row + 2);
                const float2 p45 = *reinterpret_cast<const float2*>(row + 4);
                const float2 p67 = *reinterpret_cast<const float2*>(row + 6);

                // Even taps via FFMA2 (operand pairs are natural).
                acc01[cc] = ffma2(p01, wp0[i * 3 + 0], acc01[cc]);
                acc01[cc] = ffma2(p23, wp0[i * 3 + 1], acc01[cc]);
                acc01[cc] = ffma2(p45, wp0[i * 3 + 2], acc01[cc]);
                acc23[cc] = ffma2(p23, wp1[i * 3 + 0], acc23[cc]);
                acc23[cc] = ffma2(p45, wp1[i * 3 + 1], acc23[cc]);
                acc23[cc] = ffma2(p67, wp1[i * 3 + 2], acc23[cc]);

                // Odd taps scalar: pixel p, tap j reads v[p+j].
                const float v1 = p01.y, v2 = p23.x, v3 = p23.y,
                            v4 = p45.x, v5 = p45.y, v6 = p67.x;
                // j = 1
                acc01[cc].x = fmaf(v1, wodd[0][i * 2 + 0], acc01[cc].x);
                acc01[cc].y = fmaf(v2, wodd[1][i * 2 + 0], acc01[cc].y);
                acc23[cc].x = fmaf(v3, wodd[2][i * 2 + 0], acc23[cc].x);
                acc23[cc].y = fmaf(v4, wodd[3][i * 2 + 0], acc23[cc].y);
                // j = 3
                acc01[cc].x = fmaf(v3, wodd[0][i * 2 + 1], acc01[cc].x);
                acc01[cc].y = fmaf(v4, wodd[1][i * 2 + 1], acc01[cc].y);
                acc23[cc].x = fmaf(v5, wodd[2][i * 2 + 1], acc23[cc].x);
                acc23[cc].y = fmaf(v6, wodd[3][i * 2 + 1], acc23[cc].y);
            }
        }

        #pragma unroll
        for (int cc = 0; cc < CH; cc++) {
            float4 o = {acc01[cc].x, acc01[cc].y, acc23[cc].x, acc23[cc].y};
            *reinterpret_cast<float4*>(
                &outb[((size_t)(c0 + cc) * HEIGHT + h) * WIDTH + wbase]) = o;
        }
    }
}

extern "C" void kernel_launch(void* const* d_in, const int* in_sizes, int n_in,
                              void* d_out, int out_size)
{
    const float* input       = (const float*)d_in[0];
    const float* kernel_bank = (const float*)d_in[1];
    const int*   buckets     = (const int*)d_in[2];
    float*       output      = (float*)d_out;

    dim3 block(BTX, BTY, 1);
    dim3 grid(WIDTH / TILE_OW, HEIGHT / TILE_OH, BATCH);   // (3, 12, 8)
    csconv2d_kernel<<<grid, block>>>(input, kernel_bank, buckets, output);
}